// round 6
// baseline (speedup 1.0000x reference)
#include <cuda_runtime.h>
#include <cstdint>
#include <math.h>

#define BTOK 4096
#define DIM 1024
#define HID 4096
#define NE 8
#define NSLOT (BTOK*2)
#define CAP 9216
#define MTILES (CAP/128)      // 72

// ---------------- scratch (device globals; no runtime allocation) ----------------
__device__ __align__(128) float g_xn[BTOK*DIM];            // pooled -> layernormed (tf32 RNA)
__device__ __align__(128) float g_hid[(size_t)CAP*HID];    // silu(hidden), tf32 RNA
__device__ __align__(128) float g_y[(size_t)CAP*DIM];      // expert outputs
__device__ __align__(128) float g_w1r[(size_t)NE*HID*DIM]; // RNA-rounded w1
__device__ __align__(128) float g_w2r[(size_t)NE*DIM*HID]; // RNA-rounded w2
__device__ int   g_tok[CAP];
__device__ int   g_slot[NSLOT];
__device__ float g_topw[NSLOT];
__device__ int   g_topi[NSLOT];
__device__ int   g_cnt[NE];
__device__ int   g_off[NE+1];
__device__ int   g_tile_e[MTILES];

// ---------------- helpers ----------------
__device__ __forceinline__ uint32_t cvt_tf32(float x){
    uint32_t u; asm("cvt.rna.tf32.f32 %0, %1;" : "=r"(u) : "f"(x)); return u;
}
__device__ __forceinline__ void cp16(uint32_t dst, const void* src){
    asm volatile("cp.async.cg.shared.global [%0], [%1], 16;\n" :: "r"(dst), "l"(src));
}
__device__ __forceinline__ void mma_tf32(float* c, const uint32_t* a, const uint32_t* b){
    asm volatile("mma.sync.aligned.m16n8k8.row.col.f32.tf32.tf32.f32 "
        "{%0,%1,%2,%3}, {%4,%5,%6,%7}, {%8,%9}, {%0,%1,%2,%3};"
        : "+f"(c[0]), "+f"(c[1]), "+f"(c[2]), "+f"(c[3])
        : "r"(a[0]), "r"(a[1]), "r"(a[2]), "r"(a[3]), "r"(b[0]), "r"(b[1]));
}
// swizzled float index inside a [row][32-float] smem tile
__device__ __forceinline__ int swzf(int r, int c){
    return r*32 + ((((c>>2) ^ (r & 7)) << 2) | (c & 3));
}

// ---------------- fused init + weight-round + pool ----------------
// grid = BTOK*DIM*32/256 = 524288 blocks. Each block additionally RNA-rounds
// 16 float4 of w1 and 16 float4 of w2 (524288*16 = NE*HID*DIM/4 exactly).
__global__ void pool_k(const float* __restrict__ x,
                       const float* __restrict__ w1, const float* __restrict__ w2){
    const int t = threadIdx.x;
    if (t < 32){
        size_t i = (size_t)blockIdx.x*16 + (t & 15);
        const float4* src = (t < 16) ? (const float4*)w1 : (const float4*)w2;
        float4*       dst = (t < 16) ? (float4*)g_w1r   : (float4*)g_w2r;
        float4 v = src[i];
        v.x = __uint_as_float(cvt_tf32(v.x));
        v.y = __uint_as_float(cvt_tf32(v.y));
        v.z = __uint_as_float(cvt_tf32(v.z));
        v.w = __uint_as_float(cvt_tf32(v.w));
        dst[i] = v;
    }
    if (blockIdx.x == 0){
        if (t < NE) g_cnt[t] = 0;
        if (t < MTILES) g_tile_e[t] = -1;
        for (int i = t; i < CAP; i += 256) g_tok[i] = 0;
    }
    int g = blockIdx.x*blockDim.x + t;
    int row = g >> 5, lane = g & 31;
    float2 v = ((const float2*)(x + (size_t)row*64))[lane];
    float s = v.x + v.y;
#pragma unroll
    for (int o=16;o;o>>=1) s += __shfl_xor_sync(0xffffffffu, s, o);
    if (!lane) g_xn[row] = s * (1.0f/64.0f);
}

__global__ void __launch_bounds__(256) lngate_k(const float* __restrict__ gamma,
                                                const float* __restrict__ beta,
                                                const float* __restrict__ wg,
                                                const float* __restrict__ bg){
    const int b = blockIdx.x, t = threadIdx.x;
    __shared__ float srow[DIM];
    __shared__ float rs[8], rss[8], slog[8];
    float4 v = ((const float4*)(g_xn + (size_t)b*DIM))[t];
    float s  = (v.x+v.y)+(v.z+v.w);
    float ss = (v.x*v.x+v.y*v.y)+(v.z*v.z+v.w*v.w);
#pragma unroll
    for (int o=16;o;o>>=1){ s += __shfl_xor_sync(0xffffffffu, s, o); ss += __shfl_xor_sync(0xffffffffu, ss, o); }
    const int lane = t & 31, w = t >> 5;
    if (!lane){ rs[w]=s; rss[w]=ss; }
    __syncthreads();
    float tot=0.f, tot2=0.f;
#pragma unroll
    for (int i=0;i<8;i++){ tot += rs[i]; tot2 += rss[i]; }
    const float mean = tot * (1.0f/DIM);
    const float var  = tot2 * (1.0f/DIM) - mean*mean;
    const float rinv = rsqrtf(var + 1e-5f);
    float4 g4 = ((const float4*)gamma)[t];
    float4 be4 = ((const float4*)beta)[t];
    float4 xn;
    xn.x = (v.x-mean)*rinv*g4.x + be4.x;
    xn.y = (v.y-mean)*rinv*g4.y + be4.y;
    xn.z = (v.z-mean)*rinv*g4.z + be4.z;
    xn.w = (v.w-mean)*rinv*g4.w + be4.w;
    ((float4*)srow)[t] = xn;                 // full precision for gating
    float4 xr;
    xr.x = __uint_as_float(cvt_tf32(xn.x));
    xr.y = __uint_as_float(cvt_tf32(xn.y));
    xr.z = __uint_as_float(cvt_tf32(xn.z));
    xr.w = __uint_as_float(cvt_tf32(xn.w));
    ((float4*)(g_xn + (size_t)b*DIM))[t] = xr;   // tf32-rounded for GEMM
    __syncthreads();
    const float4* wrow = (const float4*)(wg + (size_t)w*DIM);
    const float4* sr = (const float4*)srow;
    float acc = 0.f;
#pragma unroll
    for (int i=0;i<8;i++){
        int idx = lane + i*32;
        float4 a = sr[idx], ww = wrow[idx];
        acc += a.x*ww.x + a.y*ww.y + a.z*ww.z + a.w*ww.w;
    }
#pragma unroll
    for (int o=16;o;o>>=1) acc += __shfl_xor_sync(0xffffffffu, acc, o);
    if (!lane) slog[w] = acc + bg[w];
    __syncthreads();
    if (!t){
        int e0 = 0;
#pragma unroll
        for (int i=1;i<8;i++) if (slog[i] > slog[e0]) e0 = i;
        int e1 = (e0==0) ? 1 : 0;
#pragma unroll
        for (int i=0;i<8;i++) if (i!=e0 && slog[i] > slog[e1]) e1 = i;
        float z = expf(slog[e1] - slog[e0]);      // v1 <= v0
        g_topi[b*2]=e0; g_topi[b*2+1]=e1;
        g_topw[b*2]=1.0f/(1.0f+z); g_topw[b*2+1]=z/(1.0f+z);
        atomicAdd(&g_cnt[e0],1); atomicAdd(&g_cnt[e1],1);
    }
}

// fused scan + scatter: single block, smem counters
__global__ void __launch_bounds__(256) scanscatter_k(){
    __shared__ int cur[NE];
    const int t = threadIdx.x;
    if (t == 0){
        int off = 0;
        for (int e=0;e<NE;e++){
            g_off[e] = off;
            int nt = (g_cnt[e] + 127) >> 7;
            int t0 = off >> 7;
            for (int i=0;i<nt;i++) g_tile_e[t0+i] = e;
            off += nt << 7;
        }
        g_off[NE] = off;
    }
    if (t < NE) cur[t] = 0;
    __syncthreads();
    for (int i=t; i<NSLOT; i+=256){
        int e = g_topi[i];
        int p = g_off[e] + atomicAdd(&cur[e], 1);
        g_tok[p] = i >> 1;
        g_slot[i] = p;
    }
}

// ---------------- tf32 mma GEMM: CTA tile 128x256, warp tile 64x64 ----------------
// Weights pre-rounded (no cvt in mainloop). Reduced register footprint.
// smem: 4 stages x (A 128x32 + B 256x32 floats) = 192KB; 1 CTA/SM
template<int KD, int ND, bool GATHER, bool SILU>
__global__ void __launch_bounds__(256) gemm_k(const float* __restrict__ W,
                                              const float* __restrict__ bias){
    extern __shared__ float smf[];
    const int ntile = blockIdx.x, mtile = blockIdx.y;
    const int e = g_tile_e[mtile];
    if (e < 0) return;
    const int t = threadIdx.x;

    // ---- loader setup ----
    const float* aptr[4]; int aoff[4];
#pragma unroll
    for (int i=0;i<4;i++){
        int idx = t + i*256;            // 0..1023
        int r = idx >> 3, f = idx & 7;
        aoff[i] = r*32 + ((f ^ (r&7)) << 2);
        if (GATHER) aptr[i] = g_xn  + (size_t)g_tok[mtile*128 + r]*KD + f*4;
        else        aptr[i] = g_hid + (size_t)(mtile*128 + r)*KD + f*4;
    }
    const float* Wb = W + (size_t)e*ND*KD + (size_t)ntile*256*KD;
    int boffg[8], boff[8];
#pragma unroll
    for (int i=0;i<8;i++){
        int idx = t + i*256;            // 0..2047
        int r = idx >> 3, f = idx & 7;
        boffg[i] = r*KD + f*4;          // element offset from Wb (fits int32)
        boff[i]  = r*32 + ((f ^ (r&7)) << 2);
    }
    const float* bias_e = bias + (size_t)e*ND;
    uint32_t sAu = (uint32_t)__cvta_generic_to_shared(smf);

    const int NK = KD/32;
    // prologue: stages 0..2   (stage stride 12288 floats: A 4096 + B 8192)
#pragma unroll
    for (int c=0;c<3;c++){
        int ko = c*32;
#pragma unroll
        for (int i=0;i<4;i++) cp16(sAu + (uint32_t)(c*12288 + aoff[i])*4u,        aptr[i] + ko);
#pragma unroll
        for (int i=0;i<8;i++) cp16(sAu + (uint32_t)(c*12288 + 4096 + boff[i])*4u, Wb + boffg[i] + ko);
        asm volatile("cp.async.commit_group;\n");
    }

    const int w = t>>5, lane = t&31;
    const int wm = w & 1, wn = w >> 1;        // 2 x 4 warp grid; warp tile 64x64
    const int lr = lane >> 2, lc = lane & 3;
    float acc[4][8][4];
#pragma unroll
    for (int a=0;a<4;a++)
#pragma unroll
        for (int bb=0;bb<8;bb++)
#pragma unroll
            for (int c=0;c<4;c++) acc[a][bb][c] = 0.f;

    for (int kc=0; kc<NK; kc++){
        const int buf = kc & 3;
        asm volatile("cp.async.wait_group 2;\n");
        __syncthreads();
        if (kc+3 < NK){
            const int nb = (kc+3) & 3;
            const int ko = (kc+3)*32;
#pragma unroll
            for (int i=0;i<4;i++) cp16(sAu + (uint32_t)(nb*12288 + aoff[i])*4u,        aptr[i] + ko);
#pragma unroll
            for (int i=0;i<8;i++) cp16(sAu + (uint32_t)(nb*12288 + 4096 + boff[i])*4u, Wb + boffg[i] + ko);
        }
        asm volatile("cp.async.commit_group;\n");

        const float* A  = smf + buf*12288;
        const float* Bs = smf + buf*12288 + 4096;
#pragma unroll
        for (int s=0;s<4;s++){
            const int c0 = s*8 + lc;
            uint32_t bfr[8][2];
#pragma unroll
            for (int ni=0;ni<8;ni++){
                const int n = wn*64 + ni*8 + lr;
                bfr[ni][0] = __float_as_uint(Bs[swzf(n, c0)]);
                bfr[ni][1] = __float_as_uint(Bs[swzf(n, c0+4)]);
            }
#pragma unroll
            for (int mi=0;mi<4;mi++){
                uint32_t afr[4];
                const int r = wm*64 + mi*16 + lr;
                afr[0] = __float_as_uint(A[swzf(r,   c0)]);
                afr[1] = __float_as_uint(A[swzf(r+8, c0)]);
                afr[2] = __float_as_uint(A[swzf(r,   c0+4)]);
                afr[3] = __float_as_uint(A[swzf(r+8, c0+4)]);
#pragma unroll
                for (int ni=0;ni<8;ni++)
                    mma_tf32(acc[mi][ni], afr, bfr[ni]);
            }
        }
    }

    float* Out = SILU ? g_hid : g_y;
#pragma unroll
    for (int mi=0;mi<4;mi++){
        const int rb = mtile*128 + wm*64 + mi*16 + lr;
#pragma unroll
        for (int ni=0;ni<8;ni++){
            const int nb = ntile*256 + wn*64 + ni*8 + lc*2;
            const float b0 = bias_e[nb], b1v = bias_e[nb+1];
#pragma unroll
            for (int h=0; h<2; h++){
                const int p = rb + h*8;
                float v0 = acc[mi][ni][h*2+0] + b0;
                float v1 = acc[mi][ni][h*2+1] + b1v;
                if (SILU){
                    v0 = v0 / (1.0f + expf(-v0));
                    v1 = v1 / (1.0f + expf(-v1));
                    v0 = __uint_as_float(cvt_tf32(v0));
                    v1 = __uint_as_float(cvt_tf32(v1));
                }
                *(float2*)(Out + (size_t)p*ND + nb) = make_float2(v0, v1);
            }
        }
    }
}

// warp per (b,d) row — coalesced float2 residual add
__global__ void resid_k(const float* __restrict__ x, float* __restrict__ out){
    int g = blockIdx.x*blockDim.x + threadIdx.x;
    int row = g >> 5, lane = g & 31;
    int b = row >> 10, d = row & 1023;
    float f = 0.f;
    if (lane == 0){
        f = g_topw[2*b]   * g_y[(size_t)g_slot[2*b]  *DIM + d]
          + g_topw[2*b+1] * g_y[(size_t)g_slot[2*b+1]*DIM + d];
    }
    f = __shfl_sync(0xffffffffu, f, 0);
    float2 v = ((const float2*)(x + (size_t)row*64))[lane];
    v.x += f; v.y += f;
    ((float2*)(out + (size_t)row*64))[lane] = v;
}

// ---------------- launch ----------------
extern "C" void kernel_launch(void* const* d_in, const int* in_sizes, int n_in,
                              void* d_out, int out_size){
    const float* x     = (const float*)d_in[0];
    const float* gamma = (const float*)d_in[1];
    const float* beta  = (const float*)d_in[2];
    const float* wg    = (const float*)d_in[3];
    const float* bg    = (const float*)d_in[4];
    const float* w1    = (const float*)d_in[5];
    const float* b1    = (const float*)d_in[6];
    const float* w2    = (const float*)d_in[7];
    const float* b2    = (const float*)d_in[8];
    float* out = (float*)d_out;

    float *w1r, *w2r;
    cudaGetSymbolAddress((void**)&w1r, g_w1r);
    cudaGetSymbolAddress((void**)&w2r, g_w2r);

    cudaFuncSetAttribute(gemm_k<DIM, HID, true,  true >, cudaFuncAttributeMaxDynamicSharedMemorySize, 196608);
    cudaFuncSetAttribute(gemm_k<HID, DIM, false, false>, cudaFuncAttributeMaxDynamicSharedMemorySize, 196608);

    pool_k<<<(BTOK*DIM*32)/256, 256>>>(x, w1, w2);    // 1: init + weight-round + pool
    lngate_k<<<BTOK, 256>>>(gamma, beta, wg, bg);      // 2
    scanscatter_k<<<1, 256>>>();                       // 3
    gemm_k<DIM, HID, true,  true ><<<dim3(HID/256, MTILES), 256, 196608>>>(w1r, b1);   // 4 <- ncu
    gemm_k<HID, DIM, false, false><<<dim3(DIM/256, MTILES), 256, 196608>>>(w2r, b2);   // 5
    resid_k<<<(BTOK*DIM*32)/256, 256>>>(x, out);       // 6
}

// round 7
// speedup vs baseline: 1.0580x; 1.0580x over previous
#include <cuda_runtime.h>
#include <cstdint>
#include <math.h>

#define BTOK 4096
#define DIM 1024
#define HID 4096
#define NE 8
#define NSLOT (BTOK*2)
#define CAP 9216
#define MTILES (CAP/128)      // 72

// ---------------- scratch (device globals; no runtime allocation) ----------------
__device__ __align__(128) float g_xn[BTOK*DIM];            // pooled -> layernormed (tf32 RNA)
__device__ __align__(128) float g_hid[(size_t)CAP*HID];    // silu(hidden), tf32 RNA
__device__ __align__(128) float g_y[(size_t)CAP*DIM];      // expert outputs
__device__ __align__(128) float g_w1r[(size_t)NE*HID*DIM]; // RNA-rounded w1
__device__ __align__(128) float g_w2r[(size_t)NE*DIM*HID]; // RNA-rounded w2
__device__ int   g_tok[CAP];
__device__ int   g_slot[NSLOT];
__device__ float g_topw[NSLOT];
__device__ int   g_topi[NSLOT];
__device__ int   g_cnt[NE];
__device__ int   g_off[NE+1];
__device__ int   g_tile_e[MTILES];

// ---------------- helpers ----------------
__device__ __forceinline__ uint32_t cvt_tf32(float x){
    uint32_t u; asm("cvt.rna.tf32.f32 %0, %1;" : "=r"(u) : "f"(x)); return u;
}
__device__ __forceinline__ void cp16(uint32_t dst, const void* src){
    asm volatile("cp.async.cg.shared.global [%0], [%1], 16;\n" :: "r"(dst), "l"(src));
}
__device__ __forceinline__ void mma_tf32(float* c, const uint32_t* a, const uint32_t* b){
    asm volatile("mma.sync.aligned.m16n8k8.row.col.f32.tf32.tf32.f32 "
        "{%0,%1,%2,%3}, {%4,%5,%6,%7}, {%8,%9}, {%0,%1,%2,%3};"
        : "+f"(c[0]), "+f"(c[1]), "+f"(c[2]), "+f"(c[3])
        : "r"(a[0]), "r"(a[1]), "r"(a[2]), "r"(a[3]), "r"(b[0]), "r"(b[1]));
}
// swizzled float index inside a [row][32-float] smem tile
__device__ __forceinline__ int swzf(int r, int c){
    return r*32 + ((((c>>2) ^ (r & 7)) << 2) | (c & 3));
}

// ---------------- fused init + weight-round + pool ----------------
__global__ void pool_k(const float* __restrict__ x,
                       const float* __restrict__ w1, const float* __restrict__ w2){
    const int t = threadIdx.x;
    if (t < 32){
        size_t i = (size_t)blockIdx.x*16 + (t & 15);
        const float4* src = (t < 16) ? (const float4*)w1 : (const float4*)w2;
        float4*       dst = (t < 16) ? (float4*)g_w1r   : (float4*)g_w2r;
        float4 v = src[i];
        v.x = __uint_as_float(cvt_tf32(v.x));
        v.y = __uint_as_float(cvt_tf32(v.y));
        v.z = __uint_as_float(cvt_tf32(v.z));
        v.w = __uint_as_float(cvt_tf32(v.w));
        dst[i] = v;
    }
    if (blockIdx.x == 0){
        if (t < NE) g_cnt[t] = 0;
        if (t < MTILES) g_tile_e[t] = -1;
        for (int i = t; i < CAP; i += 256) g_tok[i] = 0;
    }
    int g = blockIdx.x*blockDim.x + t;
    int row = g >> 5, lane = g & 31;
    float2 v = ((const float2*)(x + (size_t)row*64))[lane];
    float s = v.x + v.y;
#pragma unroll
    for (int o=16;o;o>>=1) s += __shfl_xor_sync(0xffffffffu, s, o);
    if (!lane) g_xn[row] = s * (1.0f/64.0f);
}

__global__ void __launch_bounds__(256) lngate_k(const float* __restrict__ gamma,
                                                const float* __restrict__ beta,
                                                const float* __restrict__ wg,
                                                const float* __restrict__ bg){
    const int b = blockIdx.x, t = threadIdx.x;
    __shared__ float srow[DIM];
    __shared__ float rs[8], rss[8], slog[8];
    float4 v = ((const float4*)(g_xn + (size_t)b*DIM))[t];
    float s  = (v.x+v.y)+(v.z+v.w);
    float ss = (v.x*v.x+v.y*v.y)+(v.z*v.z+v.w*v.w);
#pragma unroll
    for (int o=16;o;o>>=1){ s += __shfl_xor_sync(0xffffffffu, s, o); ss += __shfl_xor_sync(0xffffffffu, ss, o); }
    const int lane = t & 31, w = t >> 5;
    if (!lane){ rs[w]=s; rss[w]=ss; }
    __syncthreads();
    float tot=0.f, tot2=0.f;
#pragma unroll
    for (int i=0;i<8;i++){ tot += rs[i]; tot2 += rss[i]; }
    const float mean = tot * (1.0f/DIM);
    const float var  = tot2 * (1.0f/DIM) - mean*mean;
    const float rinv = rsqrtf(var + 1e-5f);
    float4 g4 = ((const float4*)gamma)[t];
    float4 be4 = ((const float4*)beta)[t];
    float4 xn;
    xn.x = (v.x-mean)*rinv*g4.x + be4.x;
    xn.y = (v.y-mean)*rinv*g4.y + be4.y;
    xn.z = (v.z-mean)*rinv*g4.z + be4.z;
    xn.w = (v.w-mean)*rinv*g4.w + be4.w;
    ((float4*)srow)[t] = xn;                 // full precision for gating
    float4 xr;
    xr.x = __uint_as_float(cvt_tf32(xn.x));
    xr.y = __uint_as_float(cvt_tf32(xn.y));
    xr.z = __uint_as_float(cvt_tf32(xn.z));
    xr.w = __uint_as_float(cvt_tf32(xn.w));
    ((float4*)(g_xn + (size_t)b*DIM))[t] = xr;   // tf32-rounded for GEMM
    __syncthreads();
    const float4* wrow = (const float4*)(wg + (size_t)w*DIM);
    const float4* sr = (const float4*)srow;
    float acc = 0.f;
#pragma unroll
    for (int i=0;i<8;i++){
        int idx = lane + i*32;
        float4 a = sr[idx], ww = wrow[idx];
        acc += a.x*ww.x + a.y*ww.y + a.z*ww.z + a.w*ww.w;
    }
#pragma unroll
    for (int o=16;o;o>>=1) acc += __shfl_xor_sync(0xffffffffu, acc, o);
    if (!lane) slog[w] = acc + bg[w];
    __syncthreads();
    if (!t){
        int e0 = 0;
#pragma unroll
        for (int i=1;i<8;i++) if (slog[i] > slog[e0]) e0 = i;
        int e1 = (e0==0) ? 1 : 0;
#pragma unroll
        for (int i=0;i<8;i++) if (i!=e0 && slog[i] > slog[e1]) e1 = i;
        float z = expf(slog[e1] - slog[e0]);      // v1 <= v0
        g_topi[b*2]=e0; g_topi[b*2+1]=e1;
        g_topw[b*2]=1.0f/(1.0f+z); g_topw[b*2+1]=z/(1.0f+z);
        atomicAdd(&g_cnt[e0],1); atomicAdd(&g_cnt[e1],1);
    }
}

// fused scan + scatter: single block, smem counters
__global__ void __launch_bounds__(256) scanscatter_k(){
    __shared__ int cur[NE];
    const int t = threadIdx.x;
    if (t == 0){
        int off = 0;
        for (int e=0;e<NE;e++){
            g_off[e] = off;
            int nt = (g_cnt[e] + 127) >> 7;
            int t0 = off >> 7;
            for (int i=0;i<nt;i++) g_tile_e[t0+i] = e;
            off += nt << 7;
        }
        g_off[NE] = off;
    }
    if (t < NE) cur[t] = 0;
    __syncthreads();
    for (int i=t; i<NSLOT; i+=256){
        int e = g_topi[i];
        int p = g_off[e] + atomicAdd(&cur[e], 1);
        g_tok[p] = i >> 1;
        g_slot[i] = p;
    }
}

// ---------------- tf32 mma GEMM: CTA tile 128x256, warp tile 64x64 ----------------
// Loader state collapsed to scalars: for thread t the i-th load row is
// r0 + 32*i, and (r&7) is i-invariant, so both the swizzled smem offset and
// the gmem offset are affine in i. 4-stage cp.async ring, 192KB smem, 1 CTA/SM.
template<int KD, int ND, bool GATHER, bool SILU>
__global__ void __launch_bounds__(256) gemm_k(const float* __restrict__ W,
                                              const float* __restrict__ bias){
    extern __shared__ float smf[];
    const int ntile = blockIdx.x, mtile = blockIdx.y;
    const int e = g_tile_e[mtile];
    if (e < 0) return;
    const int t = threadIdx.x;

    const int r0 = t >> 3, f4 = (t & 7) * 4;                 // r0: 0..31, f4: float offset
    const int soff0 = r0*32 + (((t & 7) ^ (r0 & 7)) << 2);   // smem float offset, +i*1024

    // A gmem: GEMM1 gathers per-row (4 ptrs); GEMM2 affine single base
    const float* aptr[4];
    if (GATHER){
#pragma unroll
        for (int i=0;i<4;i++)
            aptr[i] = g_xn + (size_t)g_tok[mtile*128 + r0 + i*32]*KD + f4;
    } else {
        aptr[0] = g_hid + (size_t)(mtile*128 + r0)*KD + f4;
    }
    const float* bbase = W + (size_t)e*ND*KD + (size_t)(ntile*256 + r0)*KD + f4;
    const float* bias_e = bias + (size_t)e*ND;
    uint32_t sAu = (uint32_t)__cvta_generic_to_shared(smf);

    const int NK = KD/32;
    // prologue: stages 0..2   (stage stride 12288 floats: A 4096 + B 8192)
#pragma unroll
    for (int c=0;c<3;c++){
        const int ko = c*32;
        const uint32_t sb = sAu + (uint32_t)(c*12288 + soff0)*4u;
#pragma unroll
        for (int i=0;i<4;i++)
            cp16(sb + i*4096u, (GATHER ? aptr[i] : aptr[0] + (size_t)i*32*KD) + ko);
#pragma unroll
        for (int i=0;i<8;i++)
            cp16(sb + 16384u + i*4096u, bbase + (size_t)i*32*KD + ko);
        asm volatile("cp.async.commit_group;\n");
    }

    const int w = t>>5, lane = t&31;
    const int wm = w & 1, wn = w >> 1;        // 2 x 4 warp grid; warp tile 64x64
    const int lr = lane >> 2, lc = lane & 3;
    float acc[4][8][4];
#pragma unroll
    for (int a=0;a<4;a++)
#pragma unroll
        for (int bb=0;bb<8;bb++)
#pragma unroll
            for (int c=0;c<4;c++) acc[a][bb][c] = 0.f;

    for (int kc=0; kc<NK; kc++){
        const int buf = kc & 3;
        asm volatile("cp.async.wait_group 2;\n");
        __syncthreads();
        if (kc+3 < NK){
            const int ko = (kc+3)*32;
            const uint32_t sb = sAu + (uint32_t)(((kc+3)&3)*12288 + soff0)*4u;
#pragma unroll
            for (int i=0;i<4;i++)
                cp16(sb + i*4096u, (GATHER ? aptr[i] : aptr[0] + (size_t)i*32*KD) + ko);
#pragma unroll
            for (int i=0;i<8;i++)
                cp16(sb + 16384u + i*4096u, bbase + (size_t)i*32*KD + ko);
        }
        asm volatile("cp.async.commit_group;\n");

        const float* A  = smf + buf*12288;
        const float* Bs = smf + buf*12288 + 4096;
#pragma unroll
        for (int s=0;s<4;s++){
            const int c0 = s*8 + lc;
            uint32_t bfr[8][2];
#pragma unroll
            for (int ni=0;ni<8;ni++){
                const int n = wn*64 + ni*8 + lr;
                bfr[ni][0] = __float_as_uint(Bs[swzf(n, c0)]);
                bfr[ni][1] = __float_as_uint(Bs[swzf(n, c0+4)]);
            }
#pragma unroll
            for (int mi=0;mi<4;mi++){
                uint32_t afr[4];
                const int r = wm*64 + mi*16 + lr;
                afr[0] = __float_as_uint(A[swzf(r,   c0)]);
                afr[1] = __float_as_uint(A[swzf(r+8, c0)]);
                afr[2] = __float_as_uint(A[swzf(r,   c0+4)]);
                afr[3] = __float_as_uint(A[swzf(r+8, c0+4)]);
#pragma unroll
                for (int ni=0;ni<8;ni++)
                    mma_tf32(acc[mi][ni], afr, bfr[ni]);
            }
        }
    }

    float* Out = SILU ? g_hid : g_y;
#pragma unroll
    for (int mi=0;mi<4;mi++){
        const int rb = mtile*128 + wm*64 + mi*16 + lr;
#pragma unroll
        for (int ni=0;ni<8;ni++){
            const int nb = ntile*256 + wn*64 + ni*8 + lc*2;
            const float b0 = bias_e[nb], b1v = bias_e[nb+1];
#pragma unroll
            for (int h=0; h<2; h++){
                const int p = rb + h*8;
                float v0 = acc[mi][ni][h*2+0] + b0;
                float v1 = acc[mi][ni][h*2+1] + b1v;
                if (SILU){
                    v0 = v0 / (1.0f + expf(-v0));
                    v1 = v1 / (1.0f + expf(-v1));
                    v0 = __uint_as_float(cvt_tf32(v0));
                    v1 = __uint_as_float(cvt_tf32(v1));
                }
                *(float2*)(Out + (size_t)p*ND + nb) = make_float2(v0, v1);
            }
        }
    }
}

// warp per (b,d) row — coalesced float2 residual add
__global__ void resid_k(const float* __restrict__ x, float* __restrict__ out){
    int g = blockIdx.x*blockDim.x + threadIdx.x;
    int row = g >> 5, lane = g & 31;
    int b = row >> 10, d = row & 1023;
    float f = 0.f;
    if (lane == 0){
        f = g_topw[2*b]   * g_y[(size_t)g_slot[2*b]  *DIM + d]
          + g_topw[2*b+1] * g_y[(size_t)g_slot[2*b+1]*DIM + d];
    }
    f = __shfl_sync(0xffffffffu, f, 0);
    float2 v = ((const float2*)(x + (size_t)row*64))[lane];
    v.x += f; v.y += f;
    ((float2*)(out + (size_t)row*64))[lane] = v;
}

// ---------------- launch ----------------
extern "C" void kernel_launch(void* const* d_in, const int* in_sizes, int n_in,
                              void* d_out, int out_size){
    const float* x     = (const float*)d_in[0];
    const float* gamma = (const float*)d_in[1];
    const float* beta  = (const float*)d_in[2];
    const float* wg    = (const float*)d_in[3];
    const float* bg    = (const float*)d_in[4];
    const float* w1    = (const float*)d_in[5];
    const float* b1    = (const float*)d_in[6];
    const float* w2    = (const float*)d_in[7];
    const float* b2    = (const float*)d_in[8];
    float* out = (float*)d_out;

    float *w1r, *w2r;
    cudaGetSymbolAddress((void**)&w1r, g_w1r);
    cudaGetSymbolAddress((void**)&w2r, g_w2r);

    cudaFuncSetAttribute(gemm_k<DIM, HID, true,  true >, cudaFuncAttributeMaxDynamicSharedMemorySize, 196608);
    cudaFuncSetAttribute(gemm_k<HID, DIM, false, false>, cudaFuncAttributeMaxDynamicSharedMemorySize, 196608);

    pool_k<<<(BTOK*DIM*32)/256, 256>>>(x, w1, w2);    // 1: init + weight-round + pool
    lngate_k<<<BTOK, 256>>>(gamma, beta, wg, bg);      // 2
    scanscatter_k<<<1, 256>>>();                       // 3
    gemm_k<DIM, HID, true,  true ><<<dim3(HID/256, MTILES), 256, 196608>>>(w1r, b1);   // 4 <- ncu
    gemm_k<HID, DIM, false, false><<<dim3(DIM/256, MTILES), 256, 196608>>>(w2r, b2);   // 5
    resid_k<<<(BTOK*DIM*32)/256, 256>>>(x, out);       // 6
}

// round 8
// speedup vs baseline: 1.1917x; 1.1263x over previous
#include <cuda_runtime.h>
#include <cstdint>
#include <math.h>

#define BTOK 4096
#define DIM 1024
#define HID 4096
#define NE 8
#define NSLOT (BTOK*2)
#define CAP 9216
#define MTILES (CAP/128)      // 72

// ---------------- scratch (device globals; no runtime allocation) ----------------
__device__ __align__(128) float g_xn[BTOK*DIM];            // pooled -> layernormed (tf32 RNA)
__device__ __align__(128) float g_hid[(size_t)CAP*HID];    // silu(hidden), tf32 RNA
__device__ __align__(128) float g_y[(size_t)CAP*DIM];      // expert outputs
__device__ __align__(128) float g_w1r[(size_t)NE*HID*DIM]; // RNA-rounded w1
__device__ __align__(128) float g_w2r[(size_t)NE*DIM*HID]; // RNA-rounded w2
__device__ int   g_tok[CAP];
__device__ int   g_slot[NSLOT];
__device__ float g_topw[NSLOT];
__device__ int   g_topi[NSLOT];
__device__ int   g_cnt[NE];
__device__ int   g_off[NE+1];
__device__ int   g_tile_e[MTILES];

// ---------------- helpers ----------------
__device__ __forceinline__ uint32_t cvt_tf32(float x){
    uint32_t u; asm("cvt.rna.tf32.f32 %0, %1;" : "=r"(u) : "f"(x)); return u;
}
__device__ __forceinline__ void cp16(uint32_t dst, const void* src){
    asm volatile("cp.async.cg.shared.global [%0], [%1], 16;\n" :: "r"(dst), "l"(src));
}
__device__ __forceinline__ void mma_tf32(float* c, const uint32_t* a, const uint32_t* b){
    asm volatile("mma.sync.aligned.m16n8k8.row.col.f32.tf32.tf32.f32 "
        "{%0,%1,%2,%3}, {%4,%5,%6,%7}, {%8,%9}, {%0,%1,%2,%3};"
        : "+f"(c[0]), "+f"(c[1]), "+f"(c[2]), "+f"(c[3])
        : "r"(a[0]), "r"(a[1]), "r"(a[2]), "r"(a[3]), "r"(b[0]), "r"(b[1]));
}
// swizzled float index inside a [row][32-float] smem tile
__device__ __forceinline__ int swzf(int r, int c){
    return r*32 + ((((c>>2) ^ (r & 7)) << 2) | (c & 3));
}

// ---------------- fused init + weight-round + pool ----------------
__global__ void pool_k(const float* __restrict__ x,
                       const float* __restrict__ w1, const float* __restrict__ w2){
    const int t = threadIdx.x;
    if (t < 32){
        size_t i = (size_t)blockIdx.x*16 + (t & 15);
        const float4* src = (t < 16) ? (const float4*)w1 : (const float4*)w2;
        float4*       dst = (t < 16) ? (float4*)g_w1r   : (float4*)g_w2r;
        float4 v = src[i];
        v.x = __uint_as_float(cvt_tf32(v.x));
        v.y = __uint_as_float(cvt_tf32(v.y));
        v.z = __uint_as_float(cvt_tf32(v.z));
        v.w = __uint_as_float(cvt_tf32(v.w));
        dst[i] = v;
    }
    if (blockIdx.x == 0){
        if (t < NE) g_cnt[t] = 0;
        if (t < MTILES) g_tile_e[t] = -1;
        for (int i = t; i < CAP; i += 256) g_tok[i] = 0;
    }
    int g = blockIdx.x*blockDim.x + t;
    int row = g >> 5, lane = g & 31;
    float2 v = ((const float2*)(x + (size_t)row*64))[lane];
    float s = v.x + v.y;
#pragma unroll
    for (int o=16;o;o>>=1) s += __shfl_xor_sync(0xffffffffu, s, o);
    if (!lane) g_xn[row] = s * (1.0f/64.0f);
}

__global__ void __launch_bounds__(256) lngate_k(const float* __restrict__ gamma,
                                                const float* __restrict__ beta,
                                                const float* __restrict__ wg,
                                                const float* __restrict__ bg){
    const int b = blockIdx.x, t = threadIdx.x;
    __shared__ float srow[DIM];
    __shared__ float rs[8], rss[8], slog[8];
    float4 v = ((const float4*)(g_xn + (size_t)b*DIM))[t];
    float s  = (v.x+v.y)+(v.z+v.w);
    float ss = (v.x*v.x+v.y*v.y)+(v.z*v.z+v.w*v.w);
#pragma unroll
    for (int o=16;o;o>>=1){ s += __shfl_xor_sync(0xffffffffu, s, o); ss += __shfl_xor_sync(0xffffffffu, ss, o); }
    const int lane = t & 31, w = t >> 5;
    if (!lane){ rs[w]=s; rss[w]=ss; }
    __syncthreads();
    float tot=0.f, tot2=0.f;
#pragma unroll
    for (int i=0;i<8;i++){ tot += rs[i]; tot2 += rss[i]; }
    const float mean = tot * (1.0f/DIM);
    const float var  = tot2 * (1.0f/DIM) - mean*mean;
    const float rinv = rsqrtf(var + 1e-5f);
    float4 g4 = ((const float4*)gamma)[t];
    float4 be4 = ((const float4*)beta)[t];
    float4 xn;
    xn.x = (v.x-mean)*rinv*g4.x + be4.x;
    xn.y = (v.y-mean)*rinv*g4.y + be4.y;
    xn.z = (v.z-mean)*rinv*g4.z + be4.z;
    xn.w = (v.w-mean)*rinv*g4.w + be4.w;
    ((float4*)srow)[t] = xn;                 // full precision for gating
    float4 xr;
    xr.x = __uint_as_float(cvt_tf32(xn.x));
    xr.y = __uint_as_float(cvt_tf32(xn.y));
    xr.z = __uint_as_float(cvt_tf32(xn.z));
    xr.w = __uint_as_float(cvt_tf32(xn.w));
    ((float4*)(g_xn + (size_t)b*DIM))[t] = xr;   // tf32-rounded for GEMM
    __syncthreads();
    const float4* wrow = (const float4*)(wg + (size_t)w*DIM);
    const float4* sr = (const float4*)srow;
    float acc = 0.f;
#pragma unroll
    for (int i=0;i<8;i++){
        int idx = lane + i*32;
        float4 a = sr[idx], ww = wrow[idx];
        acc += a.x*ww.x + a.y*ww.y + a.z*ww.z + a.w*ww.w;
    }
#pragma unroll
    for (int o=16;o;o>>=1) acc += __shfl_xor_sync(0xffffffffu, acc, o);
    if (!lane) slog[w] = acc + bg[w];
    __syncthreads();
    if (!t){
        int e0 = 0;
#pragma unroll
        for (int i=1;i<8;i++) if (slog[i] > slog[e0]) e0 = i;
        int e1 = (e0==0) ? 1 : 0;
#pragma unroll
        for (int i=0;i<8;i++) if (i!=e0 && slog[i] > slog[e1]) e1 = i;
        float z = expf(slog[e1] - slog[e0]);      // v1 <= v0
        g_topi[b*2]=e0; g_topi[b*2+1]=e1;
        g_topw[b*2]=1.0f/(1.0f+z); g_topw[b*2+1]=z/(1.0f+z);
        atomicAdd(&g_cnt[e0],1); atomicAdd(&g_cnt[e1],1);
    }
}

// fused scan + scatter: single block, smem counters
__global__ void __launch_bounds__(256) scanscatter_k(){
    __shared__ int cur[NE];
    const int t = threadIdx.x;
    if (t == 0){
        int off = 0;
        for (int e=0;e<NE;e++){
            g_off[e] = off;
            int nt = (g_cnt[e] + 127) >> 7;
            int t0 = off >> 7;
            for (int i=0;i<nt;i++) g_tile_e[t0+i] = e;
            off += nt << 7;
        }
        g_off[NE] = off;
    }
    if (t < NE) cur[t] = 0;
    __syncthreads();
    for (int i=t; i<NSLOT; i+=256){
        int e = g_topi[i];
        int p = g_off[e] + atomicAdd(&cur[e], 1);
        g_tok[p] = i >> 1;
        g_slot[i] = p;
    }
}

// ---------------- tf32 mma GEMM: CTA tile 128x256, warp tile 64x64 ----------------
// Fragment double-buffering over the K-micro (s) loop to overlap LDS with mma.
// 4-stage cp.async ring, 192KB smem, 1 CTA/SM.
template<int KD, int ND, bool GATHER, bool SILU>
__global__ void __launch_bounds__(256) gemm_k(const float* __restrict__ W,
                                              const float* __restrict__ bias){
    extern __shared__ float smf[];
    const int ntile = blockIdx.x, mtile = blockIdx.y;
    const int e = g_tile_e[mtile];
    if (e < 0) return;
    const int t = threadIdx.x;

    const int r0 = t >> 3, f4 = (t & 7) * 4;
    const int soff0 = r0*32 + (((t & 7) ^ (r0 & 7)) << 2);

    const float* aptr[4];
    if (GATHER){
#pragma unroll
        for (int i=0;i<4;i++)
            aptr[i] = g_xn + (size_t)g_tok[mtile*128 + r0 + i*32]*KD + f4;
    } else {
        aptr[0] = g_hid + (size_t)(mtile*128 + r0)*KD + f4;
    }
    const float* bbase = W + (size_t)e*ND*KD + (size_t)(ntile*256 + r0)*KD + f4;
    const float* bias_e = bias + (size_t)e*ND;
    uint32_t sAu = (uint32_t)__cvta_generic_to_shared(smf);

    const int NK = KD/32;
#pragma unroll
    for (int c=0;c<3;c++){
        const int ko = c*32;
        const uint32_t sb = sAu + (uint32_t)(c*12288 + soff0)*4u;
#pragma unroll
        for (int i=0;i<4;i++)
            cp16(sb + i*4096u, (GATHER ? aptr[i] : aptr[0] + (size_t)i*32*KD) + ko);
#pragma unroll
        for (int i=0;i<8;i++)
            cp16(sb + 16384u + i*4096u, bbase + (size_t)i*32*KD + ko);
        asm volatile("cp.async.commit_group;\n");
    }

    const int w = t>>5, lane = t&31;
    const int wm = w & 1, wn = w >> 1;        // 2 x 4 warp grid; warp tile 64x64
    const int lr = lane >> 2, lc = lane & 3;
    float acc[4][8][4];
#pragma unroll
    for (int a=0;a<4;a++)
#pragma unroll
        for (int bb=0;bb<8;bb++)
#pragma unroll
            for (int c=0;c<4;c++) acc[a][bb][c] = 0.f;

    for (int kc=0; kc<NK; kc++){
        const int buf = kc & 3;
        asm volatile("cp.async.wait_group 2;\n");
        __syncthreads();
        if (kc+3 < NK){
            const int ko = (kc+3)*32;
            const uint32_t sb = sAu + (uint32_t)(((kc+3)&3)*12288 + soff0)*4u;
#pragma unroll
            for (int i=0;i<4;i++)
                cp16(sb + i*4096u, (GATHER ? aptr[i] : aptr[0] + (size_t)i*32*KD) + ko);
#pragma unroll
            for (int i=0;i<8;i++)
                cp16(sb + 16384u + i*4096u, bbase + (size_t)i*32*KD + ko);
        }
        asm volatile("cp.async.commit_group;\n");

        const float* A  = smf + buf*12288;
        const float* Bs = smf + buf*12288 + 4096;

        uint32_t bfr[2][8][2], afr[2][4][4];
        // preload s = 0 fragments
        {
            const int c0 = lc;
#pragma unroll
            for (int ni=0;ni<8;ni++){
                const int n = wn*64 + ni*8 + lr;
                bfr[0][ni][0] = __float_as_uint(Bs[swzf(n, c0)]);
                bfr[0][ni][1] = __float_as_uint(Bs[swzf(n, c0+4)]);
            }
#pragma unroll
            for (int mi=0;mi<4;mi++){
                const int r = wm*64 + mi*16 + lr;
                afr[0][mi][0] = __float_as_uint(A[swzf(r,   c0)]);
                afr[0][mi][1] = __float_as_uint(A[swzf(r+8, c0)]);
                afr[0][mi][2] = __float_as_uint(A[swzf(r,   c0+4)]);
                afr[0][mi][3] = __float_as_uint(A[swzf(r+8, c0+4)]);
            }
        }
#pragma unroll
        for (int s=0;s<4;s++){
            const int cs = s & 1, ns = cs ^ 1;
            if (s < 3){
                const int c1 = (s+1)*8 + lc;
#pragma unroll
                for (int ni=0;ni<8;ni++){
                    const int n = wn*64 + ni*8 + lr;
                    bfr[ns][ni][0] = __float_as_uint(Bs[swzf(n, c1)]);
                    bfr[ns][ni][1] = __float_as_uint(Bs[swzf(n, c1+4)]);
                }
#pragma unroll
                for (int mi=0;mi<4;mi++){
                    const int r = wm*64 + mi*16 + lr;
                    afr[ns][mi][0] = __float_as_uint(A[swzf(r,   c1)]);
                    afr[ns][mi][1] = __float_as_uint(A[swzf(r+8, c1)]);
                    afr[ns][mi][2] = __float_as_uint(A[swzf(r,   c1+4)]);
                    afr[ns][mi][3] = __float_as_uint(A[swzf(r+8, c1+4)]);
                }
            }
#pragma unroll
            for (int mi=0;mi<4;mi++)
#pragma unroll
                for (int ni=0;ni<8;ni++)
                    mma_tf32(acc[mi][ni], afr[cs][mi], bfr[cs][ni]);
        }
    }

    float* Out = SILU ? g_hid : g_y;
#pragma unroll
    for (int mi=0;mi<4;mi++){
        const int rb = mtile*128 + wm*64 + mi*16 + lr;
#pragma unroll
        for (int ni=0;ni<8;ni++){
            const int nb = ntile*256 + wn*64 + ni*8 + lc*2;
            const float b0 = bias_e[nb], b1v = bias_e[nb+1];
#pragma unroll
            for (int h=0; h<2; h++){
                const int p = rb + h*8;
                float v0 = acc[mi][ni][h*2+0] + b0;
                float v1 = acc[mi][ni][h*2+1] + b1v;
                if (SILU){
                    v0 = v0 / (1.0f + expf(-v0));
                    v1 = v1 / (1.0f + expf(-v1));
                    v0 = __uint_as_float(cvt_tf32(v0));
                    v1 = __uint_as_float(cvt_tf32(v1));
                }
                *(float2*)(Out + (size_t)p*ND + nb) = make_float2(v0, v1);
            }
        }
    }
}

// ---------------- coalesced residual ----------------
// Block = 256 consecutive (b,d) rows (one shared b). Phase 1: coalesced gather of
// both expert outputs per row into smem. Phase 2: broadcast-add over spatial dims.
__global__ void __launch_bounds__(256) resid_k(const float* __restrict__ x,
                                               float* __restrict__ out){
    __shared__ float sf[256];
    const int t = threadIdx.x;
    const int base = blockIdx.x * 256;            // first (b,d) row
    const int b = base >> 10;
    const int d = (base & 1023) + t;
    const int p0 = g_slot[2*b], p1 = g_slot[2*b+1];
    sf[t] = g_topw[2*b]   * g_y[(size_t)p0*DIM + d]
          + g_topw[2*b+1] * g_y[(size_t)p1*DIM + d];
    __syncthreads();
    const float4* xi = (const float4*)(x + (size_t)base*64);
    float4* o = (float4*)(out + (size_t)base*64);
#pragma unroll 4
    for (int i=t; i<4096; i+=256){                // 256 rows x 16 float4
        float f = sf[i >> 4];
        float4 v = xi[i];
        v.x += f; v.y += f; v.z += f; v.w += f;
        o[i] = v;
    }
}

// ---------------- launch ----------------
extern "C" void kernel_launch(void* const* d_in, const int* in_sizes, int n_in,
                              void* d_out, int out_size){
    const float* x     = (const float*)d_in[0];
    const float* gamma = (const float*)d_in[1];
    const float* beta  = (const float*)d_in[2];
    const float* wg    = (const float*)d_in[3];
    const float* bg    = (const float*)d_in[4];
    const float* w1    = (const float*)d_in[5];
    const float* b1    = (const float*)d_in[6];
    const float* w2    = (const float*)d_in[7];
    const float* b2    = (const float*)d_in[8];
    float* out = (float*)d_out;

    float *w1r, *w2r;
    cudaGetSymbolAddress((void**)&w1r, g_w1r);
    cudaGetSymbolAddress((void**)&w2r, g_w2r);

    cudaFuncSetAttribute(gemm_k<DIM, HID, true,  true >, cudaFuncAttributeMaxDynamicSharedMemorySize, 196608);
    cudaFuncSetAttribute(gemm_k<HID, DIM, false, false>, cudaFuncAttributeMaxDynamicSharedMemorySize, 196608);

    pool_k<<<(BTOK*DIM*32)/256, 256>>>(x, w1, w2);    // 1: init + weight-round + pool
    lngate_k<<<BTOK, 256>>>(gamma, beta, wg, bg);      // 2
    scanscatter_k<<<1, 256>>>();                       // 3
    gemm_k<DIM, HID, true,  true ><<<dim3(HID/256, MTILES), 256, 196608>>>(w1r, b1);   // 4 <- ncu
    gemm_k<HID, DIM, false, false><<<dim3(DIM/256, MTILES), 256, 196608>>>(w2r, b2);   // 5
    resid_k<<<(BTOK*DIM)/256, 256>>>(x, out);          // 6
}